// round 1
// baseline (speedup 1.0000x reference)
#include <cuda_runtime.h>
#include <cstdint>

// Problem constants (from reference): B=8, N=500000, H=W=512, HALF_CENTOR=true
#define BB    8
#define NPTS  500000
#define HH    512
#define WW    512
#define NCELL (BB * HH * WW)   // 2,097,152 cells

// Scratch (no cudaMalloc allowed): 8 MB + 8 MB device globals.
__device__ unsigned int g_min[NCELL];
__device__ int          g_cnt[NCELL];

// Order-preserving float <-> uint mapping so unsigned atomicMin == float min.
__device__ __forceinline__ unsigned int enc_f(float f) {
    unsigned int u = __float_as_uint(f);
    return (u & 0x80000000u) ? ~u : (u | 0x80000000u);
}
__device__ __forceinline__ float dec_f(unsigned int u) {
    return __uint_as_float((u & 0x80000000u) ? (u & 0x7FFFFFFFu) : ~u);
}

// ---------------------------------------------------------------------------
// Kernel 1: init scratch. NCELL/4 threads, vectorized 16B stores.
// ---------------------------------------------------------------------------
__global__ void k_init() {
    int i = blockIdx.x * blockDim.x + threadIdx.x;
    if (i < NCELL / 4) {
        reinterpret_cast<uint4*>(g_min)[i] = make_uint4(~0u, ~0u, ~0u, ~0u);
        reinterpret_cast<int4*>(g_cnt)[i]  = make_int4(0, 0, 0, 0);
    }
}

// ---------------------------------------------------------------------------
// Kernel 2: scatter. grid = (ceil(N/256), B). One point per thread.
// points layout [B, N, 2] float32 -> coalesced float2 loads.
// ---------------------------------------------------------------------------
__global__ void k_scatter(const float* __restrict__ points,
                          const float* __restrict__ costs) {
    int n = blockIdx.x * blockDim.x + threadIdx.x;
    int b = blockIdx.y;
    if (n >= NPTS) return;
    long long gi = (long long)b * NPTS + n;
    float2 p = reinterpret_cast<const float2*>(points)[gi];
    // HALF_CENTOR: floor(x + 0.5)
    int ix = (int)floorf(p.x + 0.5f);
    int iy = (int)floorf(p.y + 0.5f);
    if ((unsigned)ix < (unsigned)WW && (unsigned)iy < (unsigned)HH) {
        int cell = (b * HH + iy) * WW + ix;
        float c = costs[gi];
        atomicMin(&g_min[cell], enc_f(c));  // RED (no return used)
        atomicAdd(&g_cnt[cell], 1);         // RED
    }
}

// ---------------------------------------------------------------------------
// Kernel 3: finalize. NCELL/4 threads, vectorized.
// out_cost[cell] = cnt>0 ? decoded_min : default_cost
// out_mask[cell] = (float)(cnt - 1)
// ---------------------------------------------------------------------------
__global__ void k_final(float* __restrict__ out_cost,
                        float* __restrict__ out_mask,
                        const float* __restrict__ default_cost) {
    int i = blockIdx.x * blockDim.x + threadIdx.x;
    if (i >= NCELL / 4) return;
    uint4 m = reinterpret_cast<const uint4*>(g_min)[i];
    int4  c = reinterpret_cast<const int4*>(g_cnt)[i];
    float d = __ldg(default_cost);
    float4 cost;
    cost.x = (c.x > 0) ? dec_f(m.x) : d;
    cost.y = (c.y > 0) ? dec_f(m.y) : d;
    cost.z = (c.z > 0) ? dec_f(m.z) : d;
    cost.w = (c.w > 0) ? dec_f(m.w) : d;
    reinterpret_cast<float4*>(out_cost)[i] = cost;
    if (out_mask) {
        float4 mk = make_float4((float)(c.x - 1), (float)(c.y - 1),
                                (float)(c.z - 1), (float)(c.w - 1));
        reinterpret_cast<float4*>(out_mask)[i] = mk;
    }
}

// ---------------------------------------------------------------------------
// Launcher. Inputs (metadata order): points[B,N,2] f32, costs[B,N] f32,
// default_cost f32 scalar, height i32, width i32.
// Output: [cost (B*H*W f32) | mask (B*H*W, count-1, emitted as f32)].
// ---------------------------------------------------------------------------
extern "C" void kernel_launch(void* const* d_in, const int* in_sizes, int n_in,
                              void* d_out, int out_size) {
    const float* points       = (const float*)d_in[0];
    const float* costs        = (const float*)d_in[1];
    const float* default_cost = (const float*)d_in[2];

    float* out_cost = (float*)d_out;
    float* out_mask = (out_size >= 2 * NCELL) ? out_cost + NCELL : nullptr;

    const int T = 256;
    k_init<<<(NCELL / 4 + T - 1) / T, T>>>();

    dim3 grid((NPTS + T - 1) / T, BB);
    k_scatter<<<grid, T>>>(points, costs);

    k_final<<<(NCELL / 4 + T - 1) / T, T>>>(out_cost, out_mask, default_cost);
}

// round 2
// speedup vs baseline: 1.0461x; 1.0461x over previous
#include <cuda_runtime.h>
#include <cstdint>

// Problem constants (from reference): B=8, N=500000, H=W=512, HALF_CENTOR=true
#define BB    8
#define NPTS  500000
#define HH    512
#define WW    512
#define NCELL (BB * HH * WW)   // 2,097,152 cells

// Interleaved per-cell scratch: .x = max of ~enc_f(cost) (0 == empty sentinel),
// .y = count (0 == empty). Zero-initialized at module load; the finalize kernel
// restores zeros after each use, so every kernel_launch call sees zeros on entry.
__device__ uint2 g_cell[NCELL];   // 16 MB, stays L2-resident

// Order-preserving float -> uint (monotone increasing).
__device__ __forceinline__ unsigned int enc_f(float f) {
    unsigned int u = __float_as_uint(f);
    return (u & 0x80000000u) ? ~u : (u | 0x80000000u);
}
// Inverse of enc_f.
__device__ __forceinline__ float dec_f(unsigned int u) {
    return __uint_as_float((u & 0x80000000u) ? (u & 0x7FFFFFFFu) : ~u);
}

// ---------------------------------------------------------------------------
// Scatter: 2 points per thread. grid = (ceil(N/2/256), B).
// atomicMax on m = ~enc_f(c): larger m == smaller cost, sentinel 0 loses to
// every finite cost. atomicAdd for counts. Both results unused -> RED form.
// ---------------------------------------------------------------------------
__global__ void k_scatter(const float4* __restrict__ points2,  // [B, N/2] of (x0,y0,x1,y1)
                          const float2* __restrict__ costs2) { // [B, N/2]
    int t = blockIdx.x * blockDim.x + threadIdx.x;
    int b = blockIdx.y;
    if (t >= NPTS / 2) return;
    int gi = b * (NPTS / 2) + t;
    float4 p = points2[gi];
    float2 c = costs2[gi];

    int ix0 = (int)floorf(p.x + 0.5f);
    int iy0 = (int)floorf(p.y + 0.5f);
    if ((unsigned)ix0 < (unsigned)WW && (unsigned)iy0 < (unsigned)HH) {
        int cell = (b * HH + iy0) * WW + ix0;
        atomicMax(&g_cell[cell].x, ~enc_f(c.x));
        atomicAdd(&g_cell[cell].y, 1u);
    }
    int ix1 = (int)floorf(p.z + 0.5f);
    int iy1 = (int)floorf(p.w + 0.5f);
    if ((unsigned)ix1 < (unsigned)WW && (unsigned)iy1 < (unsigned)HH) {
        int cell = (b * HH + iy1) * WW + ix1;
        atomicMax(&g_cell[cell].x, ~enc_f(c.y));
        atomicAdd(&g_cell[cell].y, 1u);
    }
}

// ---------------------------------------------------------------------------
// Finalize: 4 cells per thread. Decodes min / default, emits mask = count-1,
// and RESTORES the zero sentinel so the next call starts clean.
// ---------------------------------------------------------------------------
__global__ void k_final(float* __restrict__ out_cost,
                        float* __restrict__ out_mask,
                        const float* __restrict__ default_cost) {
    int i = blockIdx.x * blockDim.x + threadIdx.x;   // cell group (4 cells)
    if (i >= NCELL / 4) return;
    const uint4* cellv = reinterpret_cast<const uint4*>(g_cell);
    uint4 a = cellv[2 * i];       // cells 4i, 4i+1 : (m0,c0,m1,c1)
    uint4 bq = cellv[2 * i + 1];  // cells 4i+2, 4i+3

    float d = __ldg(default_cost);
    float4 cost;
    cost.x = a.y  ? dec_f(~a.x)  : d;
    cost.y = a.w  ? dec_f(~a.z)  : d;
    cost.z = bq.y ? dec_f(~bq.x) : d;
    cost.w = bq.w ? dec_f(~bq.z) : d;
    reinterpret_cast<float4*>(out_cost)[i] = cost;

    if (out_mask) {
        float4 mk = make_float4((float)((int)a.y - 1),  (float)((int)a.w - 1),
                                (float)((int)bq.y - 1), (float)((int)bq.w - 1));
        reinterpret_cast<float4*>(out_mask)[i] = mk;
    }

    // restore zero sentinels (L2-resident stores)
    uint4 z = make_uint4(0u, 0u, 0u, 0u);
    uint4* cellw = reinterpret_cast<uint4*>(g_cell);
    cellw[2 * i]     = z;
    cellw[2 * i + 1] = z;
}

// ---------------------------------------------------------------------------
// Launcher. Inputs: points[B,N,2] f32, costs[B,N] f32, default_cost f32,
// height i32, width i32. Output: [cost | mask] as f32.
// ---------------------------------------------------------------------------
extern "C" void kernel_launch(void* const* d_in, const int* in_sizes, int n_in,
                              void* d_out, int out_size) {
    const float4* points2      = (const float4*)d_in[0];
    const float2* costs2       = (const float2*)d_in[1];
    const float*  default_cost = (const float*)d_in[2];

    float* out_cost = (float*)d_out;
    float* out_mask = (out_size >= 2 * NCELL) ? out_cost + NCELL : nullptr;

    const int T = 256;
    dim3 sg((NPTS / 2 + T - 1) / T, BB);
    k_scatter<<<sg, T>>>(points2, costs2);

    k_final<<<(NCELL / 4 + T - 1) / T, T>>>(out_cost, out_mask, default_cost);
}